// round 7
// baseline (speedup 1.0000x reference)
#include <cuda_runtime.h>
#include <cuda_fp16.h>
#include <cstdint>

#define L_DIM 2048
#define D_DIM 64
#define N_BH 32
#define JT 128
#define NJT (L_DIM / JT)     // 16
#define NTH 256

#define OFF_A 0
#define OFF_B(b) (32768 + (b) * 16384)
#define SMEM_TOTAL 65536

#define NELEM (N_BH * L_DIM * D_DIM)

__device__ __align__(16) __half g_A[NELEM];
__device__ __align__(16) __half g_B[NELEM];

__device__ __forceinline__ uint32_t smem_u32(const void* p) {
    uint32_t a;
    asm("{ .reg .u64 t; cvta.to.shared.u64 t, %1; cvt.u32.u64 %0, t; }" : "=r"(a) : "l"(p));
    return a;
}
__device__ __forceinline__ float lg2f(float x) {
    float y; asm("lg2.approx.f32 %0, %1;" : "=f"(y) : "f"(x)); return y;
}
__device__ __forceinline__ float ex2f(float x) {
    float y; asm("ex2.approx.f32 %0, %1;" : "=f"(y) : "f"(x)); return y;
}
__device__ __forceinline__ float pow23_mufu(float a) {
    float x = fmaxf(a, 0.0f) + 1e-12f;
    return ex2f(lg2f(x) * 0.666666667f);
}
__device__ __forceinline__ float pow23_fma(float a) {
    float x = fmaxf(a, 0.0f) + 1e-12f;
    float w = __int_as_float(0x54A2FC96 - (__float_as_int(x) / 3));
    float t = x * w;
    float u = fmaf(-(1.0f / 3.0f), t * w * w, 4.0f / 3.0f);
    w = w * u;
    t = x * w;
    u = fmaf(-(1.0f / 3.0f), t * w * w, 4.0f / 3.0f);
    return t * u;
}
__device__ __forceinline__ void ldsm4(uint32_t* r, uint32_t addr) {
    asm volatile("ldmatrix.sync.aligned.m8n8.x4.shared.b16 {%0,%1,%2,%3}, [%4];"
                 : "=r"(r[0]), "=r"(r[1]), "=r"(r[2]), "=r"(r[3]) : "r"(addr));
}
__device__ __forceinline__ void mma16816(float* c, const uint32_t* a, const uint32_t* b) {
    asm volatile(
        "mma.sync.aligned.m16n8k16.row.col.f32.f16.f16.f32 "
        "{%0,%1,%2,%3}, {%4,%5,%6,%7}, {%8,%9}, {%0,%1,%2,%3};"
        : "+f"(c[0]), "+f"(c[1]), "+f"(c[2]), "+f"(c[3])
        : "r"(a[0]), "r"(a[1]), "r"(a[2]), "r"(a[3]), "r"(b[0]), "r"(b[1]));
}
__device__ __forceinline__ void cpa16(uint32_t dst, const void* src) {
    asm volatile("cp.async.cg.shared.global [%0], [%1], 16;" :: "r"(dst), "l"(src) : "memory");
}
__device__ __forceinline__ void cpa_commit() {
    asm volatile("cp.async.commit_group;" ::: "memory");
}
__device__ __forceinline__ void cpa_wait1() {
    asm volatile("cp.async.wait_group 1;" ::: "memory");
}

__global__ void __launch_bounds__(NTH)
prep_kernel(const float* __restrict__ kin, const float* __restrict__ src,
            const float* __restrict__ dst)
{
    int gid = blockIdx.x * NTH + threadIdx.x;
    int rowg = gid >> 2;
    int q = gid & 3;
    int row = rowg & (L_DIM - 1);
    float s = sqrtf(src[rowg] + 1e-12f);
    float d = sqrtf(dst[rowg] + 1e-12f);
    const float* kp = kin + (size_t)rowg * D_DIM + q * 16;
    const int perm = (row & 7) << 3;
    const size_t rbase = (size_t)rowg * D_DIM;

    #pragma unroll
    for (int g = 0; g < 2; ++g) {
        float4 v0 = *(const float4*)(kp + g * 8);
        float4 v1 = *(const float4*)(kp + g * 8 + 4);
        __half2 a0 = __floats2half2_rn(v0.x * s, v0.y * s);
        __half2 a1 = __floats2half2_rn(v0.z * s, v0.w * s);
        __half2 a2 = __floats2half2_rn(v1.x * s, v1.y * s);
        __half2 a3 = __floats2half2_rn(v1.z * s, v1.w * s);
        __half2 b0 = __floats2half2_rn(v0.x * d, v0.y * d);
        __half2 b1 = __floats2half2_rn(v0.z * d, v0.w * d);
        __half2 b2 = __floats2half2_rn(v1.x * d, v1.y * d);
        __half2 b3 = __floats2half2_rn(v1.z * d, v1.w * d);
        int edst = (q * 16 + g * 8) ^ perm;
        *(uint4*)(g_A + rbase + edst) = make_uint4(*(uint32_t*)&a0, *(uint32_t*)&a1,
                                                   *(uint32_t*)&a2, *(uint32_t*)&a3);
        *(uint4*)(g_B + rbase + edst) = make_uint4(*(uint32_t*)&b0, *(uint32_t*)&b1,
                                                   *(uint32_t*)&b2, *(uint32_t*)&b3);
    }
}

__device__ __forceinline__ void copyB(uint32_t sbase, int buf, size_t bbase, int jt, int tid)
{
    #pragma unroll
    for (int it = 0; it < 4; ++it) {
        int idx = tid + it * NTH;
        int row = idx >> 3, seg = idx & 7;
        cpa16(sbase + OFF_B(buf) + (uint32_t)(row * 128 + seg * 16),
              g_B + bbase + (size_t)(jt * JT + row) * D_DIM + seg * 8);
    }
}

__global__ void __launch_bounds__(NTH, 2)
mha_fp16(float* __restrict__ out)
{
    extern __shared__ char smem[];
    const uint32_t sbase = smem_u32(smem);
    const int tid = threadIdx.x;
    const int warp = tid >> 5;
    const int lane = tid & 31;
    const int q = lane & 3;
    const int bh = blockIdx.y;
    const int bx = blockIdx.x;

    const int rbase0 = 128 * bx;                 // band 0 rows (warps 0-3)
    const int rbase1 = L_DIM - 128 * (bx + 1);   // band 1 rows (warps 4-7)

    const size_t khead = (size_t)bh * L_DIM * D_DIM;
    const size_t bbase = khead;

    // A tile: 2 bands x 128 rows x 128B
    #pragma unroll
    for (int it = 0; it < 8; ++it) {
        int idx = tid + it * NTH;
        int row = idx >> 3, seg = idx & 7;
        int grow = (row < 128) ? (rbase0 + row) : (rbase1 + row - 128);
        cpa16(sbase + OFF_A + (uint32_t)(row * 128 + seg * 16),
              g_A + khead + (size_t)grow * D_DIM + seg * 8);
    }
    copyB(sbase, 0, bbase, 0, tid);
    cpa_commit();
    copyB(sbase, 1, bbase, 1, tid);
    cpa_commit();

    // warp geometry
    const int band = warp >> 2, wl = warp & 3;
    const int rbaseg = band ? rbase1 : rbase0;   // global rows rbaseg+wl*32 .. +31
    const int rming = rbaseg + wl * 32;
    const int dt = rming >> 7;                    // diagonal tile idx; jt<dt pure zero
    const int rsm = band * 128 + wl * 32;         // smem row base

    // coalesced zero pre-store of columns [0, dt*128) for this warp's 32 rows
    // (128 floats per cb step: 32 lanes x float4, stride 128 floats)
    {
        float4 z = make_float4(0.f, 0.f, 0.f, 0.f);
        for (int r = 0; r < 32; ++r) {
            float* orow = out + ((size_t)bh * L_DIM + rming + r) * L_DIM + lane * 4;
            for (int cb = 0; cb < dt; ++cb)
                *(float4*)(orow + cb * 128) = z;
        }
    }

    const int ar0 = rsm + ((lane >> 3) & 1) * 8 + (lane & 7);
    const int ar1 = ar0 + 16;
    const int a_kb = ((lane >> 4) & 1) * 16;
    const int ax   = (ar0 & 7) << 4;
    const int br   = ((lane >> 4) & 1) * 8 + (lane & 7);
    const int b_kb = ((lane >> 3) & 1) * 16;
    const int bx2  = (br & 7) << 4;

    cpa_wait1();
    __syncthreads();

    uint32_t afr0[4][4], afr1[4][4];
    #pragma unroll
    for (int ks = 0; ks < 4; ++ks) {
        const int ka = ((ks * 32) | a_kb) ^ ax;
        ldsm4(afr0[ks], sbase + OFF_A + ar0 * 128 + ka);
        ldsm4(afr1[ks], sbase + OFF_A + ar1 * 128 + ka);
    }

    float c_up[2] = {0.0f, 0.0f}, c_dn[2] = {0.0f, 0.0f};

    for (int jt = 0; jt < NJT; ++jt) {
        if (jt) { cpa_wait1(); __syncthreads(); }
        const uint32_t B = sbase + OFF_B(jt & 1);
        const bool zt = (jt < dt);
        const bool mtile = (jt == dt);
        float zu[2] = {0.f, 0.f}, zd[2] = {0.f, 0.f};

        #pragma unroll
        for (int h = 0; h < 2; ++h) {
            float acc[2][8][4];
            #pragma unroll
            for (int m = 0; m < 2; ++m)
                #pragma unroll
                for (int n = 0; n < 8; ++n)
                    #pragma unroll
                    for (int c = 0; c < 4; ++c) acc[m][n][c] = 0.0f;

            #pragma unroll
            for (int ks = 0; ks < 4; ++ks) {
                const int kb2 = ((ks * 32) | b_kb) ^ bx2;
                #pragma unroll
                for (int cgl = 0; cgl < 4; ++cgl) {
                    const int cg = h * 4 + cgl;
                    uint32_t bf[4];
                    ldsm4(bf, B + (uint32_t)((cg * 16 + br) * 128 + kb2));
                    mma16816(acc[0][2 * cgl],     afr0[ks], bf);
                    mma16816(acc[0][2 * cgl + 1], afr0[ks], bf + 2);
                    mma16816(acc[1][2 * cgl],     afr1[ks], bf);
                    mma16816(acc[1][2 * cgl + 1], afr1[ks], bf + 2);
                }
            }

            if (h == 1) {
                __syncthreads();
                if (jt + 2 < NJT) copyB(sbase, jt & 1, bbase, jt + 2, tid);
                cpa_commit();
            }

            if (zt) {
                // zero tile: carry sums only (no scan/select/store)
                #pragma unroll
                for (int m = 0; m < 2; ++m) {
                    #pragma unroll
                    for (int nb = 0; nb < 8; ++nb) {
                        float y0, y1, z0, z1;
                        if (nb & 1) {
                            y0 = pow23_fma(acc[m][nb][0]); y1 = pow23_fma(acc[m][nb][1]);
                            z0 = pow23_fma(acc[m][nb][2]); z1 = pow23_fma(acc[m][nb][3]);
                        } else {
                            y0 = pow23_mufu(acc[m][nb][0]); y1 = pow23_mufu(acc[m][nb][1]);
                            z0 = pow23_mufu(acc[m][nb][2]); z1 = pow23_mufu(acc[m][nb][3]);
                        }
                        zu[m] += y0 + y1;
                        zd[m] += z0 + z1;
                    }
                }
            } else if (mtile) {
                // diagonal tile: full masked path
                #pragma unroll
                for (int m = 0; m < 2; ++m) {
                    const int iu = rming + m * 16 + (lane >> 2);
                    const int idn = iu + 8;
                    float* oru = out + ((size_t)bh * L_DIM + iu) * L_DIM;
                    float* ord = oru + 8 * L_DIM;
                    #pragma unroll
                    for (int nb = 0; nb < 8; ++nb) {
                        const int j0 = jt * JT + h * 64 + nb * 8 + q * 2;
                        float y0, y1, z0, z1;
                        if (nb & 1) {
                            y0 = pow23_fma(acc[m][nb][0]); y1 = pow23_fma(acc[m][nb][1]);
                            z0 = pow23_fma(acc[m][nb][2]); z1 = pow23_fma(acc[m][nb][3]);
                        } else {
                            y0 = pow23_mufu(acc[m][nb][0]); y1 = pow23_mufu(acc[m][nb][1]);
                            z0 = pow23_mufu(acc[m][nb][2]); z1 = pow23_mufu(acc[m][nb][3]);
                        }
                        {
                            float v = y0 + y1, sc = v;
                            float u1 = __shfl_up_sync(0xffffffffu, sc, 1, 4); if (q >= 1) sc += u1;
                            float u2 = __shfl_up_sync(0xffffffffu, sc, 2, 4); if (q >= 2) sc += u2;
                            float tot = __shfl_sync(0xffffffffu, sc, 3, 4);
                            float base = c_up[m] + (sc - v);
                            float2 o;
                            o.x = (j0     >= iu) ? base + y0 : 0.0f;
                            o.y = (j0 + 1 >= iu) ? base + v  : 0.0f;
                            *(float2*)(oru + j0) = o;
                            c_up[m] += tot;
                        }
                        {
                            float v = z0 + z1, sc = v;
                            float u1 = __shfl_up_sync(0xffffffffu, sc, 1, 4); if (q >= 1) sc += u1;
                            float u2 = __shfl_up_sync(0xffffffffu, sc, 2, 4); if (q >= 2) sc += u2;
                            float tot = __shfl_sync(0xffffffffu, sc, 3, 4);
                            float base = c_dn[m] + (sc - v);
                            float2 o;
                            o.x = (j0     >= idn) ? base + z0 : 0.0f;
                            o.y = (j0 + 1 >= idn) ? base + v  : 0.0f;
                            *(float2*)(ord + j0) = o;
                            c_dn[m] += tot;
                        }
                    }
                }
            } else {
                // fully above diagonal: no masks
                #pragma unroll
                for (int m = 0; m < 2; ++m) {
                    const int iu = rming + m * 16 + (lane >> 2);
                    float* oru = out + ((size_t)bh * L_DIM + iu) * L_DIM;
                    float* ord = oru + 8 * L_DIM;
                    #pragma unroll
                    for (int nb = 0; nb < 8; ++nb) {
                        const int j0 = jt * JT + h * 64 + nb * 8 + q * 2;
                        float y0, y1, z0, z1;
                        if (nb & 1) {
                            y0 = pow23_fma(acc[m][nb][0]); y1 = pow23_fma(acc[m][nb][1]);
                            z0 = pow23_fma(acc[m][nb][2]); z1 = pow23_fma(acc[m][nb][3]);
                        } else {
                            y0 = pow23_mufu(acc[m][nb][0]); y1 = pow23_mufu(acc[m][nb][1]);
                            z0 = pow23_mufu(acc[m][nb][2]); z1 = pow23_mufu(acc[m][nb][3]);
                        }
                        {
                            float v = y0 + y1, sc = v;
                            float u1 = __shfl_up_sync(0xffffffffu, sc, 1, 4); if (q >= 1) sc += u1;
                            float u2 = __shfl_up_sync(0xffffffffu, sc, 2, 4); if (q >= 2) sc += u2;
                            float tot = __shfl_sync(0xffffffffu, sc, 3, 4);
                            float base = c_up[m] + (sc - v);
                            float2 o; o.x = base + y0; o.y = base + v;
                            *(float2*)(oru + j0) = o;
                            c_up[m] += tot;
                        }
                        {
                            float v = z0 + z1, sc = v;
                            float u1 = __shfl_up_sync(0xffffffffu, sc, 1, 4); if (q >= 1) sc += u1;
                            float u2 = __shfl_up_sync(0xffffffffu, sc, 2, 4); if (q >= 2) sc += u2;
                            float tot = __shfl_sync(0xffffffffu, sc, 3, 4);
                            float base = c_dn[m] + (sc - v);
                            float2 o; o.x = base + z0; o.y = base + v;
                            *(float2*)(ord + j0) = o;
                            c_dn[m] += tot;
                        }
                    }
                }
            }
        }

        if (zt) {
            #pragma unroll
            for (int m = 0; m < 2; ++m) {
                float t = zu[m];
                t += __shfl_xor_sync(0xffffffffu, t, 1, 4);
                t += __shfl_xor_sync(0xffffffffu, t, 2, 4);
                c_up[m] += t;
                float s2 = zd[m];
                s2 += __shfl_xor_sync(0xffffffffu, s2, 1, 4);
                s2 += __shfl_xor_sync(0xffffffffu, s2, 2, 4);
                c_dn[m] += s2;
            }
        }
    }
}

extern "C" void kernel_launch(void* const* d_in, const int* in_sizes, int n_in,
                              void* d_out, int out_size) {
    const float* k    = (const float*)d_in[0];
    const float* src  = (const float*)d_in[1];
    const float* dest = (const float*)d_in[2];
    float* out = (float*)d_out;

    prep_kernel<<<(N_BH * L_DIM * 4) / NTH, NTH>>>(k, src, dest);

    cudaFuncSetAttribute(mha_fp16,
                         cudaFuncAttributeMaxDynamicSharedMemorySize, SMEM_TOTAL);
    dim3 grid(8, N_BH);   // 8 band-pair CTAs x 32 bh = 256 CTAs
    mha_fp16<<<grid, NTH, SMEM_TOTAL>>>(out);
}

// round 8
// speedup vs baseline: 1.3704x; 1.3704x over previous
#include <cuda_runtime.h>
#include <cuda_fp16.h>
#include <cstdint>

#define L_DIM 2048
#define D_DIM 64
#define N_BH 32
#define ROWS 256
#define JT 128
#define NJT (L_DIM / JT)     // 16
#define NTH 256

#define OFF_A 0
#define OFF_B(b) (32768 + (b) * 16384)
#define SMEM_TOTAL 65536

#define NELEM (N_BH * L_DIM * D_DIM)

typedef unsigned long long ull;

__device__ __align__(16) __half g_A[NELEM];
__device__ __align__(16) __half g_B[NELEM];

__device__ __forceinline__ uint32_t smem_u32(const void* p) {
    uint32_t a;
    asm("{ .reg .u64 t; cvta.to.shared.u64 t, %1; cvt.u32.u64 %0, t; }" : "=r"(a) : "l"(p));
    return a;
}
__device__ __forceinline__ float lg2f(float x) {
    float y; asm("lg2.approx.f32 %0, %1;" : "=f"(y) : "f"(x)); return y;
}
__device__ __forceinline__ float ex2f(float x) {
    float y; asm("ex2.approx.f32 %0, %1;" : "=f"(y) : "f"(x)); return y;
}
// MUFU path: (relu(a))^(2/3); lg2(0) = -inf -> ex2(-inf) = 0 (matches eps'd ref to 1e-8 abs)
__device__ __forceinline__ float pow23_mufu(float a) {
    return ex2f(lg2f(fmaxf(a, 0.0f)) * 0.666666667f);
}
__device__ __forceinline__ ull pk2(float lo, float hi) {
    ull r;
    asm("mov.b64 %0, {%1, %2};" : "=l"(r) : "r"(__float_as_uint(lo)), "r"(__float_as_uint(hi)));
    return r;
}
__device__ __forceinline__ void upk2(ull v, float& lo, float& hi) {
    uint32_t a, b;
    asm("mov.b64 {%0, %1}, %2;" : "=r"(a), "=r"(b) : "l"(v));
    lo = __uint_as_float(a); hi = __uint_as_float(b);
}
__device__ __forceinline__ ull mul2(ull a, ull b) {
    ull d; asm("mul.rn.f32x2 %0, %1, %2;" : "=l"(d) : "l"(a), "l"(b)); return d;
}
__device__ __forceinline__ ull fma2p(ull a, ull b, ull c) {
    ull d; asm("fma.rn.f32x2 %0, %1, %2, %3;" : "=l"(d) : "l"(a), "l"(b), "l"(c)); return d;
}
// FMA-pipe packed pow23 on two values (rcbrt seed + 2 Newton iters, f32x2)
__device__ __forceinline__ void pow23_fma2(float a, float b, float& ya, float& yb) {
    float xa = fmaxf(a, 0.0f), xb = fmaxf(b, 0.0f);
    float wa = __int_as_float(0x54A2FC96 - (__float_as_int(xa) / 3));
    float wb = __int_as_float(0x54A2FC96 - (__float_as_int(xb) / 3));
    ull x2 = pk2(xa, xb), w2 = pk2(wa, wb);
    const ull m13 = pk2(-1.0f / 3.0f, -1.0f / 3.0f);
    const ull f43 = pk2(4.0f / 3.0f, 4.0f / 3.0f);
    ull t2 = mul2(x2, w2);
    ull r2 = mul2(mul2(t2, w2), w2);
    ull u2 = fma2p(r2, m13, f43);
    w2 = mul2(w2, u2);
    t2 = mul2(x2, w2);
    r2 = mul2(mul2(t2, w2), w2);
    u2 = fma2p(r2, m13, f43);
    ull y2 = mul2(t2, u2);
    upk2(y2, ya, yb);
}
__device__ __forceinline__ void ldsm4(uint32_t* r, uint32_t addr) {
    asm volatile("ldmatrix.sync.aligned.m8n8.x4.shared.b16 {%0,%1,%2,%3}, [%4];"
                 : "=r"(r[0]), "=r"(r[1]), "=r"(r[2]), "=r"(r[3]) : "r"(addr));
}
__device__ __forceinline__ void mma16816(float* c, const uint32_t* a, const uint32_t* b) {
    asm volatile(
        "mma.sync.aligned.m16n8k16.row.col.f32.f16.f16.f32 "
        "{%0,%1,%2,%3}, {%4,%5,%6,%7}, {%8,%9}, {%0,%1,%2,%3};"
        : "+f"(c[0]), "+f"(c[1]), "+f"(c[2]), "+f"(c[3])
        : "r"(a[0]), "r"(a[1]), "r"(a[2]), "r"(a[3]), "r"(b[0]), "r"(b[1]));
}
__device__ __forceinline__ void cpa16(uint32_t dst, const void* src) {
    asm volatile("cp.async.cg.shared.global [%0], [%1], 16;" :: "r"(dst), "l"(src) : "memory");
}
__device__ __forceinline__ void cpa_commit() {
    asm volatile("cp.async.commit_group;" ::: "memory");
}
__device__ __forceinline__ void cpa_wait1() {
    asm volatile("cp.async.wait_group 1;" ::: "memory");
}

__global__ void __launch_bounds__(NTH)
prep_kernel(const float* __restrict__ kin, const float* __restrict__ src,
            const float* __restrict__ dst)
{
    int gid = blockIdx.x * NTH + threadIdx.x;
    int rowg = gid >> 2;
    int q = gid & 3;
    int row = rowg & (L_DIM - 1);
    float s = sqrtf(src[rowg] + 1e-12f);
    float d = sqrtf(dst[rowg] + 1e-12f);
    const float* kp = kin + (size_t)rowg * D_DIM + q * 16;
    const int perm = (row & 7) << 3;
    const size_t rbase = (size_t)rowg * D_DIM;

    #pragma unroll
    for (int g = 0; g < 2; ++g) {
        float4 v0 = *(const float4*)(kp + g * 8);
        float4 v1 = *(const float4*)(kp + g * 8 + 4);
        __half2 a0 = __floats2half2_rn(v0.x * s, v0.y * s);
        __half2 a1 = __floats2half2_rn(v0.z * s, v0.w * s);
        __half2 a2 = __floats2half2_rn(v1.x * s, v1.y * s);
        __half2 a3 = __floats2half2_rn(v1.z * s, v1.w * s);
        __half2 b0 = __floats2half2_rn(v0.x * d, v0.y * d);
        __half2 b1 = __floats2half2_rn(v0.z * d, v0.w * d);
        __half2 b2 = __floats2half2_rn(v1.x * d, v1.y * d);
        __half2 b3 = __floats2half2_rn(v1.z * d, v1.w * d);
        int edst = (q * 16 + g * 8) ^ perm;
        *(uint4*)(g_A + rbase + edst) = make_uint4(*(uint32_t*)&a0, *(uint32_t*)&a1,
                                                   *(uint32_t*)&a2, *(uint32_t*)&a3);
        *(uint4*)(g_B + rbase + edst) = make_uint4(*(uint32_t*)&b0, *(uint32_t*)&b1,
                                                   *(uint32_t*)&b2, *(uint32_t*)&b3);
    }
}

__device__ __forceinline__ void copyB(uint32_t sbase, int buf, size_t bbase, int jt, int tid)
{
    #pragma unroll
    for (int it = 0; it < 4; ++it) {
        int idx = tid + it * NTH;
        int row = idx >> 3, seg = idx & 7;
        cpa16(sbase + OFF_B(buf) + (uint32_t)(row * 128 + seg * 16),
              g_B + bbase + (size_t)(jt * JT + row) * D_DIM + seg * 8);
    }
}

// pow23 on one acc unit (4 values), pipe-alternating by nb parity
__device__ __forceinline__ void unit_pow23(const float* a, int nb,
                                           float& y0, float& y1, float& z0, float& z1) {
    if (nb & 1) {
        pow23_fma2(a[0], a[1], y0, y1);
        pow23_fma2(a[2], a[3], z0, z1);
    } else {
        y0 = pow23_mufu(a[0]); y1 = pow23_mufu(a[1]);
        z0 = pow23_mufu(a[2]); z1 = pow23_mufu(a[3]);
    }
}

__global__ void __launch_bounds__(NTH, 2)
mha_fp16(float* __restrict__ out)
{
    extern __shared__ char smem[];
    const uint32_t sbase = smem_u32(smem);
    const int tid = threadIdx.x;
    const int warp = tid >> 5;
    const int lane = tid & 31;
    const int q = lane & 3;
    const int bh = blockIdx.y;
    // SM-pair balance: co-resident CTAs are bx and (bx+4)&7 -> pair heavy with light
    const int bxr = blockIdx.x;
    const int bxe = (bxr < 4) ? bxr : (11 - bxr);
    const int i0 = bxe * ROWS;

    const size_t khead = (size_t)bh * L_DIM * D_DIM;
    const size_t abase = khead + (size_t)i0 * D_DIM;
    const size_t bbase = khead;

    #pragma unroll
    for (int it = 0; it < 8; ++it) {
        int idx = tid + it * NTH;
        int row = idx >> 3, seg = idx & 7;
        cpa16(sbase + OFF_A + (uint32_t)(row * 128 + seg * 16),
              g_A + abase + (size_t)row * D_DIM + seg * 8);
    }
    copyB(sbase, 0, bbase, 0, tid);
    cpa_commit();
    copyB(sbase, 1, bbase, 1, tid);
    cpa_commit();

    const int rb  = warp * 32;
    const int rming = i0 + rb;                  // warp's 32 rows
    const int dt = rming >> 7;                  // diagonal tile index
    const int ar0 = rb + ((lane >> 3) & 1) * 8 + (lane & 7);
    const int ar1 = ar0 + 16;
    const int a_kb = ((lane >> 4) & 1) * 16;
    const int ax   = (ar0 & 7) << 4;
    const int br   = ((lane >> 4) & 1) * 8 + (lane & 7);
    const int b_kb = ((lane >> 3) & 1) * 16;
    const int bx2  = (br & 7) << 4;

    cpa_wait1();
    __syncthreads();

    uint32_t afr0[4][4], afr1[4][4];
    #pragma unroll
    for (int ks = 0; ks < 4; ++ks) {
        const int ka = ((ks * 32) | a_kb) ^ ax;
        ldsm4(afr0[ks], sbase + OFF_A + ar0 * 128 + ka);
        ldsm4(afr1[ks], sbase + OFF_A + ar1 * 128 + ka);
    }

    float c_up[2] = {0.0f, 0.0f}, c_dn[2] = {0.0f, 0.0f};

    for (int jt = 0; jt < NJT; ++jt) {
        if (jt) { cpa_wait1(); __syncthreads(); }
        const uint32_t B = sbase + OFF_B(jt & 1);
        const bool zt = (jt < dt);
        const bool mt = (jt == dt);
        float zu[2] = {0.f, 0.f}, zd[2] = {0.f, 0.f};

        #pragma unroll
        for (int h = 0; h < 2; ++h) {
            float acc[2][8][4];
            #pragma unroll
            for (int m = 0; m < 2; ++m)
                #pragma unroll
                for (int n = 0; n < 8; ++n)
                    #pragma unroll
                    for (int c = 0; c < 4; ++c) acc[m][n][c] = 0.0f;

            #pragma unroll
            for (int ks = 0; ks < 4; ++ks) {
                const int kb2 = ((ks * 32) | b_kb) ^ bx2;
                #pragma unroll
                for (int cgl = 0; cgl < 4; ++cgl) {
                    const int cg = h * 4 + cgl;
                    uint32_t bf[4];
                    ldsm4(bf, B + (uint32_t)((cg * 16 + br) * 128 + kb2));
                    mma16816(acc[0][2 * cgl],     afr0[ks], bf);
                    mma16816(acc[0][2 * cgl + 1], afr0[ks], bf + 2);
                    mma16816(acc[1][2 * cgl],     afr1[ks], bf);
                    mma16816(acc[1][2 * cgl + 1], afr1[ks], bf + 2);
                }
            }

            if (h == 1) {   // uniform: every warp, every path
                __syncthreads();
                if (jt + 2 < NJT) copyB(sbase, jt & 1, bbase, jt + 2, tid);
                cpa_commit();
            }

            if (zt) {
                // zero regime (whole CTA together): carry sums only
                #pragma unroll
                for (int m = 0; m < 2; ++m)
                    #pragma unroll
                    for (int nb = 0; nb < 8; ++nb) {
                        float y0, y1, z0, z1;
                        unit_pow23(acc[m][nb], nb, y0, y1, z0, z1);
                        zu[m] += y0 + y1;
                        zd[m] += z0 + z1;
                    }
            } else if (mt) {
                // diagonal tile: masked path
                #pragma unroll
                for (int m = 0; m < 2; ++m) {
                    const int iu = rming + m * 16 + (lane >> 2);
                    const int idn = iu + 8;
                    float* oru = out + ((size_t)bh * L_DIM + iu) * L_DIM;
                    float* ord = oru + 8 * L_DIM;
                    #pragma unroll
                    for (int nb = 0; nb < 8; ++nb) {
                        const int j0 = jt * JT + h * 64 + nb * 8 + q * 2;
                        float y0, y1, z0, z1;
                        unit_pow23(acc[m][nb], nb, y0, y1, z0, z1);
                        {
                            float v = y0 + y1, sc = v;
                            float u1 = __shfl_up_sync(0xffffffffu, sc, 1, 4); if (q >= 1) sc += u1;
                            float u2 = __shfl_up_sync(0xffffffffu, sc, 2, 4); if (q >= 2) sc += u2;
                            float tot = __shfl_sync(0xffffffffu, sc, 3, 4);
                            float base = c_up[m] + (sc - v);
                            float2 o;
                            o.x = (j0     >= iu) ? base + y0 : 0.0f;
                            o.y = (j0 + 1 >= iu) ? base + v  : 0.0f;
                            *(float2*)(oru + j0) = o;
                            c_up[m] += tot;
                        }
                        {
                            float v = z0 + z1, sc = v;
                            float u1 = __shfl_up_sync(0xffffffffu, sc, 1, 4); if (q >= 1) sc += u1;
                            float u2 = __shfl_up_sync(0xffffffffu, sc, 2, 4); if (q >= 2) sc += u2;
                            float tot = __shfl_sync(0xffffffffu, sc, 3, 4);
                            float base = c_dn[m] + (sc - v);
                            float2 o;
                            o.x = (j0     >= idn) ? base + z0 : 0.0f;
                            o.y = (j0 + 1 >= idn) ? base + v  : 0.0f;
                            *(float2*)(ord + j0) = o;
                            c_dn[m] += tot;
                        }
                    }
                }
            } else {
                // above diagonal: unmasked
                #pragma unroll
                for (int m = 0; m < 2; ++m) {
                    const int iu = rming + m * 16 + (lane >> 2);
                    float* oru = out + ((size_t)bh * L_DIM + iu) * L_DIM;
                    float* ord = oru + 8 * L_DIM;
                    #pragma unroll
                    for (int nb = 0; nb < 8; ++nb) {
                        const int j0 = jt * JT + h * 64 + nb * 8 + q * 2;
                        float y0, y1, z0, z1;
                        unit_pow23(acc[m][nb], nb, y0, y1, z0, z1);
                        {
                            float v = y0 + y1, sc = v;
                            float u1 = __shfl_up_sync(0xffffffffu, sc, 1, 4); if (q >= 1) sc += u1;
                            float u2 = __shfl_up_sync(0xffffffffu, sc, 2, 4); if (q >= 2) sc += u2;
                            float tot = __shfl_sync(0xffffffffu, sc, 3, 4);
                            float base = c_up[m] + (sc - v);
                            float2 o; o.x = base + y0; o.y = base + v;
                            *(float2*)(oru + j0) = o;
                            c_up[m] += tot;
                        }
                        {
                            float v = z0 + z1, sc = v;
                            float u1 = __shfl_up_sync(0xffffffffu, sc, 1, 4); if (q >= 1) sc += u1;
                            float u2 = __shfl_up_sync(0xffffffffu, sc, 2, 4); if (q >= 2) sc += u2;
                            float tot = __shfl_sync(0xffffffffu, sc, 3, 4);
                            float base = c_dn[m] + (sc - v);
                            float2 o; o.x = base + z0; o.y = base + v;
                            *(float2*)(ord + j0) = o;
                            c_dn[m] += tot;
                        }
                    }
                }
            }
        }

        if (zt) {
            // fold lane-group sums into carries
            #pragma unroll
            for (int m = 0; m < 2; ++m) {
                float t = zu[m];
                t += __shfl_xor_sync(0xffffffffu, t, 1, 4);
                t += __shfl_xor_sync(0xffffffffu, t, 2, 4);
                c_up[m] += t;
                float s2 = zd[m];
                s2 += __shfl_xor_sync(0xffffffffu, s2, 1, 4);
                s2 += __shfl_xor_sync(0xffffffffu, s2, 2, 4);
                c_dn[m] += s2;
            }
            // coalesced zero stores for this 32x128 tile (32 x STG.128)
            float4 z4 = make_float4(0.f, 0.f, 0.f, 0.f);
            float* obase = out + ((size_t)bh * L_DIM + rming) * L_DIM + jt * JT + lane * 4;
            #pragma unroll 4
            for (int r = 0; r < 32; ++r)
                *(float4*)(obase + (size_t)r * L_DIM) = z4;
        }
    }
}

extern "C" void kernel_launch(void* const* d_in, const int* in_sizes, int n_in,
                              void* d_out, int out_size) {
    const float* k    = (const float*)d_in[0];
    const float* src  = (const float*)d_in[1];
    const float* dest = (const float*)d_in[2];
    float* out = (float*)d_out;

    prep_kernel<<<(N_BH * L_DIM * 4) / NTH, NTH>>>(k, src, dest);

    cudaFuncSetAttribute(mha_fp16,
                         cudaFuncAttributeMaxDynamicSharedMemorySize, SMEM_TOTAL);
    dim3 grid(8, N_BH);   // 8 i-blocks x 32 bh = 256 CTAs
    mha_fp16<<<grid, NTH, SMEM_TOTAL>>>(out);
}

// round 9
// speedup vs baseline: 1.5166x; 1.1068x over previous
#include <cuda_runtime.h>
#include <cuda_fp16.h>
#include <cstdint>

#define L_DIM 2048
#define D_DIM 64
#define N_BH 32
#define ROWS 128              // per CTA
#define JT 128
#define NJT (L_DIM / JT)      // 16
#define NTH 256

#define OFF_A 0
#define OFF_B(b) (16384 + (b) * 16384)
#define SMEM_TOTAL 49152

#define NELEM (N_BH * L_DIM * D_DIM)

typedef unsigned long long ull;

__device__ __align__(16) __half g_A[NELEM];
__device__ __align__(16) __half g_B[NELEM];

__device__ __forceinline__ uint32_t smem_u32(const void* p) {
    uint32_t a;
    asm("{ .reg .u64 t; cvta.to.shared.u64 t, %1; cvt.u32.u64 %0, t; }" : "=r"(a) : "l"(p));
    return a;
}
__device__ __forceinline__ float lg2f(float x) {
    float y; asm("lg2.approx.f32 %0, %1;" : "=f"(y) : "f"(x)); return y;
}
__device__ __forceinline__ float ex2f(float x) {
    float y; asm("ex2.approx.f32 %0, %1;" : "=f"(y) : "f"(x)); return y;
}
__device__ __forceinline__ float pow23_mufu(float a) {
    return ex2f(lg2f(fmaxf(a, 0.0f)) * 0.666666667f);
}
__device__ __forceinline__ ull pk2(float lo, float hi) {
    ull r;
    asm("mov.b64 %0, {%1, %2};" : "=l"(r) : "r"(__float_as_uint(lo)), "r"(__float_as_uint(hi)));
    return r;
}
__device__ __forceinline__ void upk2(ull v, float& lo, float& hi) {
    uint32_t a, b;
    asm("mov.b64 {%0, %1}, %2;" : "=r"(a), "=r"(b) : "l"(v));
    lo = __uint_as_float(a); hi = __uint_as_float(b);
}
__device__ __forceinline__ ull mul2(ull a, ull b) {
    ull d; asm("mul.rn.f32x2 %0, %1, %2;" : "=l"(d) : "l"(a), "l"(b)); return d;
}
__device__ __forceinline__ ull fma2p(ull a, ull b, ull c) {
    ull d; asm("fma.rn.f32x2 %0, %1, %2, %3;" : "=l"(d) : "l"(a), "l"(b), "l"(c)); return d;
}
__device__ __forceinline__ void pow23_fma2(float a, float b, float& ya, float& yb) {
    float xa = fmaxf(a, 0.0f), xb = fmaxf(b, 0.0f);
    float wa = __int_as_float(0x54A2FC96 - (__float_as_int(xa) / 3));
    float wb = __int_as_float(0x54A2FC96 - (__float_as_int(xb) / 3));
    ull x2 = pk2(xa, xb), w2 = pk2(wa, wb);
    const ull m13 = pk2(-1.0f / 3.0f, -1.0f / 3.0f);
    const ull f43 = pk2(4.0f / 3.0f, 4.0f / 3.0f);
    ull t2 = mul2(x2, w2);
    ull r2 = mul2(mul2(t2, w2), w2);
    ull u2 = fma2p(r2, m13, f43);
    w2 = mul2(w2, u2);
    t2 = mul2(x2, w2);
    r2 = mul2(mul2(t2, w2), w2);
    u2 = fma2p(r2, m13, f43);
    ull y2 = mul2(t2, u2);
    upk2(y2, ya, yb);
}
__device__ __forceinline__ void ldsm4(uint32_t* r, uint32_t addr) {
    asm volatile("ldmatrix.sync.aligned.m8n8.x4.shared.b16 {%0,%1,%2,%3}, [%4];"
                 : "=r"(r[0]), "=r"(r[1]), "=r"(r[2]), "=r"(r[3]) : "r"(addr));
}
__device__ __forceinline__ void mma16816(float* c, const uint32_t* a, const uint32_t* b) {
    asm volatile(
        "mma.sync.aligned.m16n8k16.row.col.f32.f16.f16.f32 "
        "{%0,%1,%2,%3}, {%4,%5,%6,%7}, {%8,%9}, {%0,%1,%2,%3};"
        : "+f"(c[0]), "+f"(c[1]), "+f"(c[2]), "+f"(c[3])
        : "r"(a[0]), "r"(a[1]), "r"(a[2]), "r"(a[3]), "r"(b[0]), "r"(b[1]));
}
__device__ __forceinline__ void cpa16(uint32_t dst, const void* src) {
    asm volatile("cp.async.cg.shared.global [%0], [%1], 16;" :: "r"(dst), "l"(src) : "memory");
}
__device__ __forceinline__ void cpa_commit() {
    asm volatile("cp.async.commit_group;" ::: "memory");
}
__device__ __forceinline__ void cpa_wait1() {
    asm volatile("cp.async.wait_group 1;" ::: "memory");
}

__global__ void __launch_bounds__(NTH)
prep_kernel(const float* __restrict__ kin, const float* __restrict__ src,
            const float* __restrict__ dst)
{
    int gid = blockIdx.x * NTH + threadIdx.x;
    int rowg = gid >> 2;
    int q = gid & 3;
    int row = rowg & (L_DIM - 1);
    float s = sqrtf(src[rowg] + 1e-12f);
    float d = sqrtf(dst[rowg] + 1e-12f);
    const float* kp = kin + (size_t)rowg * D_DIM + q * 16;
    const int perm = (row & 7) << 3;
    const size_t rbase = (size_t)rowg * D_DIM;

    #pragma unroll
    for (int g = 0; g < 2; ++g) {
        float4 v0 = *(const float4*)(kp + g * 8);
        float4 v1 = *(const float4*)(kp + g * 8 + 4);
        __half2 a0 = __floats2half2_rn(v0.x * s, v0.y * s);
        __half2 a1 = __floats2half2_rn(v0.z * s, v0.w * s);
        __half2 a2 = __floats2half2_rn(v1.x * s, v1.y * s);
        __half2 a3 = __floats2half2_rn(v1.z * s, v1.w * s);
        __half2 b0 = __floats2half2_rn(v0.x * d, v0.y * d);
        __half2 b1 = __floats2half2_rn(v0.z * d, v0.w * d);
        __half2 b2 = __floats2half2_rn(v1.x * d, v1.y * d);
        __half2 b3 = __floats2half2_rn(v1.z * d, v1.w * d);
        int edst = (q * 16 + g * 8) ^ perm;
        *(uint4*)(g_A + rbase + edst) = make_uint4(*(uint32_t*)&a0, *(uint32_t*)&a1,
                                                   *(uint32_t*)&a2, *(uint32_t*)&a3);
        *(uint4*)(g_B + rbase + edst) = make_uint4(*(uint32_t*)&b0, *(uint32_t*)&b1,
                                                   *(uint32_t*)&b2, *(uint32_t*)&b3);
    }
}

__device__ __forceinline__ void copyB(uint32_t sbase, int buf, size_t bbase, int jt, int tid)
{
    #pragma unroll
    for (int it = 0; it < 4; ++it) {
        int idx = tid + it * NTH;
        int row = idx >> 3, seg = idx & 7;
        cpa16(sbase + OFF_B(buf) + (uint32_t)(row * 128 + seg * 16),
              g_B + bbase + (size_t)(jt * JT + row) * D_DIM + seg * 8);
    }
}

__device__ __forceinline__ void unit_pow23(const float* a, int nb,
                                           float& y0, float& y1, float& z0, float& z1) {
    if (nb & 1) {
        pow23_fma2(a[0], a[1], y0, y1);
        pow23_fma2(a[2], a[3], z0, z1);
    } else {
        y0 = pow23_mufu(a[0]); y1 = pow23_mufu(a[1]);
        z0 = pow23_mufu(a[2]); z1 = pow23_mufu(a[3]);
    }
}

__global__ void __launch_bounds__(NTH, 3)
mha_fp16(float* __restrict__ out)
{
    extern __shared__ char smem[];
    const uint32_t sbase = smem_u32(smem);
    const int tid = threadIdx.x;
    const int warp = tid >> 5;
    const int lane = tid & 31;
    const int q = lane & 3;
    const int bh = blockIdx.y;
    // co-residency balance: same-SM CTAs are bx, bx+4, bx+8, bx+12 (mod 16);
    // map each group of 4 to {x, 15-x, y, 15-y}
    const int bxr = blockIdx.x;
    {
    }
    const int low2 = bxr & 3, hi2 = bxr >> 2;
    const int gbase = low2 * 2 + (hi2 >> 1);
    const int bxe = (hi2 & 1) ? (15 - gbase) : gbase;
    const int i0 = bxe * ROWS;

    const size_t khead = (size_t)bh * L_DIM * D_DIM;
    const size_t abase = khead + (size_t)i0 * D_DIM;
    const size_t bbase = khead;

    // A tile: 128 rows x 128B
    #pragma unroll
    for (int it = 0; it < 4; ++it) {
        int idx = tid + it * NTH;
        int row = idx >> 3, seg = idx & 7;
        cpa16(sbase + OFF_A + (uint32_t)(row * 128 + seg * 16),
              g_A + abase + (size_t)row * D_DIM + seg * 8);
    }
    copyB(sbase, 0, bbase, 0, tid);
    cpa_commit();
    copyB(sbase, 1, bbase, 1, tid);
    cpa_commit();

    const int rb = warp * 16;                 // warp's 16 rows (smem)
    const int rming = i0 + rb;                // global
    const int dt = i0 >> 7;                   // diagonal tile idx (CTA-uniform)
    const int ar0 = rb + ((lane >> 3) & 1) * 8 + (lane & 7);
    const int a_kb = ((lane >> 4) & 1) * 16;
    const int ax   = (ar0 & 7) << 4;
    const int br   = ((lane >> 4) & 1) * 8 + (lane & 7);
    const int b_kb = ((lane >> 3) & 1) * 16;
    const int bx2  = (br & 7) << 4;

    cpa_wait1();
    __syncthreads();

    uint32_t afr[4][4];
    #pragma unroll
    for (int ks = 0; ks < 4; ++ks)
        ldsm4(afr[ks], sbase + OFF_A + ar0 * 128 + (((ks * 32) | a_kb) ^ ax));

    const int iu = rming + (lane >> 2);
    const int idn = iu + 8;
    float* const oru_base = out + ((size_t)bh * L_DIM + iu) * L_DIM;
    float* const ord_base = oru_base + 8 * L_DIM;

    float c_up = 0.0f, c_dn = 0.0f;

    for (int jt = 0; jt < NJT; ++jt) {
        if (jt) { cpa_wait1(); __syncthreads(); }
        const uint32_t B = sbase + OFF_B(jt & 1);
        const bool zt = (jt < dt);
        const bool mt = (jt == dt);
        float zu = 0.f, zd = 0.f;

        #pragma unroll
        for (int h = 0; h < 2; ++h) {
            float acc[8][4];
            #pragma unroll
            for (int n = 0; n < 8; ++n)
                #pragma unroll
                for (int c = 0; c < 4; ++c) acc[n][c] = 0.0f;

            #pragma unroll
            for (int ks = 0; ks < 4; ++ks) {
                const int kb2 = ((ks * 32) | b_kb) ^ bx2;
                #pragma unroll
                for (int cgl = 0; cgl < 4; ++cgl) {
                    const int cg = h * 4 + cgl;
                    uint32_t bf[4];
                    ldsm4(bf, B + (uint32_t)((cg * 16 + br) * 128 + kb2));
                    mma16816(acc[2 * cgl],     afr[ks], bf);
                    mma16816(acc[2 * cgl + 1], afr[ks], bf + 2);
                }
            }

            if (h == 1) {
                __syncthreads();
                if (jt + 2 < NJT) copyB(sbase, jt & 1, bbase, jt + 2, tid);
                cpa_commit();
            }

            if (zt) {
                #pragma unroll
                for (int nb = 0; nb < 8; ++nb) {
                    float y0, y1, z0, z1;
                    unit_pow23(acc[nb], nb, y0, y1, z0, z1);
                    zu += y0 + y1;
                    zd += z0 + z1;
                }
            } else if (mt) {
                #pragma unroll
                for (int nb = 0; nb < 8; ++nb) {
                    const int j0 = jt * JT + h * 64 + nb * 8 + q * 2;
                    float y0, y1, z0, z1;
                    unit_pow23(acc[nb], nb, y0, y1, z0, z1);
                    {
                        float v = y0 + y1, sc = v;
                        float u1 = __shfl_up_sync(0xffffffffu, sc, 1, 4); if (q >= 1) sc += u1;
                        float u2 = __shfl_up_sync(0xffffffffu, sc, 2, 4); if (q >= 2) sc += u2;
                        float tot = __shfl_sync(0xffffffffu, sc, 3, 4);
                        float base = c_up + (sc - v);
                        float2 o;
                        o.x = (j0     >= iu) ? base + y0 : 0.0f;
                        o.y = (j0 + 1 >= iu) ? base + v  : 0.0f;
                        *(float2*)(oru_base + j0) = o;
                        c_up += tot;
                    }
                    {
                        float v = z0 + z1, sc = v;
                        float u1 = __shfl_up_sync(0xffffffffu, sc, 1, 4); if (q >= 1) sc += u1;
                        float u2 = __shfl_up_sync(0xffffffffu, sc, 2, 4); if (q >= 2) sc += u2;
                        float tot = __shfl_sync(0xffffffffu, sc, 3, 4);
                        float base = c_dn + (sc - v);
                        float2 o;
                        o.x = (j0     >= idn) ? base + z0 : 0.0f;
                        o.y = (j0 + 1 >= idn) ? base + v  : 0.0f;
                        *(float2*)(ord_base + j0) = o;
                        c_dn += tot;
                    }
                }
            } else {
                #pragma unroll
                for (int nb = 0; nb < 8; ++nb) {
                    const int j0 = jt * JT + h * 64 + nb * 8 + q * 2;
                    float y0, y1, z0, z1;
                    unit_pow23(acc[nb], nb, y0, y1, z0, z1);
                    {
                        float v = y0 + y1, sc = v;
                        float u1 = __shfl_up_sync(0xffffffffu, sc, 1, 4); if (q >= 1) sc += u1;
                        float u2 = __shfl_up_sync(0xffffffffu, sc, 2, 4); if (q >= 2) sc += u2;
                        float tot = __shfl_sync(0xffffffffu, sc, 3, 4);
                        float base = c_up + (sc - v);
                        float2 o; o.x = base + y0; o.y = base + v;
                        *(float2*)(oru_base + j0) = o;
                        c_up += tot;
                    }
                    {
                        float v = z0 + z1, sc = v;
                        float u1 = __shfl_up_sync(0xffffffffu, sc, 1, 4); if (q >= 1) sc += u1;
                        float u2 = __shfl_up_sync(0xffffffffu, sc, 2, 4); if (q >= 2) sc += u2;
                        float tot = __shfl_sync(0xffffffffu, sc, 3, 4);
                        float base = c_dn + (sc - v);
                        float2 o; o.x = base + z0; o.y = base + v;
                        *(float2*)(ord_base + j0) = o;
                        c_dn += tot;
                    }
                }
            }
        }

        if (zt) {
            float t = zu;
            t += __shfl_xor_sync(0xffffffffu, t, 1, 4);
            t += __shfl_xor_sync(0xffffffffu, t, 2, 4);
            c_up += t;
            float s2 = zd;
            s2 += __shfl_xor_sync(0xffffffffu, s2, 1, 4);
            s2 += __shfl_xor_sync(0xffffffffu, s2, 2, 4);
            c_dn += s2;
            // coalesced zero stores for this warp's 16x128 tile
            float4 z4 = make_float4(0.f, 0.f, 0.f, 0.f);
            float* obase = out + ((size_t)bh * L_DIM + rming) * L_DIM + jt * JT + lane * 4;
            #pragma unroll 4
            for (int r = 0; r < 16; ++r)
                *(float4*)(obase + (size_t)r * L_DIM) = z4;
        }
    }
}

extern "C" void kernel_launch(void* const* d_in, const int* in_sizes, int n_in,
                              void* d_out, int out_size) {
    const float* k    = (const float*)d_in[0];
    const float* src  = (const float*)d_in[1];
    const float* dest = (const float*)d_in[2];
    float* out = (float*)d_out;

    prep_kernel<<<(N_BH * L_DIM * 4) / NTH, NTH>>>(k, src, dest);

    cudaFuncSetAttribute(mha_fp16,
                         cudaFuncAttributeMaxDynamicSharedMemorySize, SMEM_TOTAL);
    dim3 grid(16, N_BH);   // 16 i-blocks x 32 bh = 512 CTAs
    mha_fp16<<<grid, NTH, SMEM_TOTAL>>>(out);
}